// round 1
// baseline (speedup 1.0000x reference)
#include <cuda_runtime.h>

namespace {
constexpr int W = 512;
constexpr int H = 512;
constexpr int OW = 506;
constexpr int OH = 506;
constexpr int CH = 96;          // 32 batch * 3 channels
constexpr int BH = 32;          // output rows per block (band height)
constexpr int NBANDS = (OH + BH - 1) / BH;  // 16
constexpr int THREADS = 128;

constexpr float C1 = 0.01f * 0.01f;       // (K1*DATA_RANGE)^2
constexpr float C2 = 0.03f * 0.03f;       // (K2*DATA_RANGE)^2
constexpr float INV_NP = 1.0f / 49.0f;
constexpr float COV_NORM = 49.0f / 48.0f;
}

__device__ double g_accum;

__global__ void ssim_zero() { g_accum = 0.0; }

__global__ void ssim_final(float* out) {
    out[0] = (float)(g_accum / ((double)CH * (double)OH * (double)OW));
}

__global__ __launch_bounds__(THREADS) void ssim_main(const float* __restrict__ X,
                                                     const float* __restrict__ Y) {
    const int ch = blockIdx.y;
    const int band = blockIdx.x;
    const float* __restrict__ x = X + (size_t)ch * H * W;
    const float* __restrict__ y = Y + (size_t)ch * H * W;
    const int r0 = band * BH;
    const int rEnd = min(r0 + BH, OH);

    // column-sum arrays, padded so float4 reads up to index 519 stay in bounds
    __shared__ __align__(16) float s_sx[W + 8];
    __shared__ __align__(16) float s_sy[W + 8];
    __shared__ __align__(16) float s_sxx[W + 8];
    __shared__ __align__(16) float s_syy[W + 8];
    __shared__ __align__(16) float s_sxy[W + 8];
    __shared__ float red[THREADS];

    const int t = threadIdx.x;

    // vertical rolling sums for 4 columns per thread
    float sx[4], sy[4], sxx[4], syy[4], sxy[4];
#pragma unroll
    for (int j = 0; j < 4; j++) { sx[j] = sy[j] = sxx[j] = syy[j] = sxy[j] = 0.0f; }

#pragma unroll
    for (int rr = 0; rr < 7; rr++) {
#pragma unroll
        for (int j = 0; j < 4; j++) {
            const int c = t + j * THREADS;
            const float xv = x[(r0 + rr) * W + c];
            const float yv = y[(r0 + rr) * W + c];
            sx[j] += xv;
            sy[j] += yv;
            sxx[j] = fmaf(xv, xv, sxx[j]);
            syy[j] = fmaf(yv, yv, syy[j]);
            sxy[j] = fmaf(xv, yv, sxy[j]);
        }
    }

    float acc = 0.0f;
    const int oc0 = 4 * t;  // first output column handled by this thread

    for (int r = r0; r < rEnd; r++) {
        if (r > r0) {
            // roll vertical sums: +row(r+6), -row(r-1)  (old row hits L1)
#pragma unroll
            for (int j = 0; j < 4; j++) {
                const int c = t + j * THREADS;
                const float xn = x[(r + 6) * W + c];
                const float yn = y[(r + 6) * W + c];
                const float xo = x[(r - 1) * W + c];
                const float yo = y[(r - 1) * W + c];
                sx[j] += xn - xo;
                sy[j] += yn - yo;
                sxx[j] += xn * xn - xo * xo;
                syy[j] += yn * yn - yo * yo;
                sxy[j] += xn * yn - xo * yo;
            }
            __syncthreads();  // WAR vs previous iteration's phase-B reads
        }

#pragma unroll
        for (int j = 0; j < 4; j++) {
            const int c = t + j * THREADS;
            s_sx[c] = sx[j];
            s_sy[c] = sy[j];
            s_sxx[c] = sxx[j];
            s_syy[c] = syy[j];
            s_sxy[c] = sxy[j];
        }
        __syncthreads();

        // phase B: horizontal 7-window sums for 4 consecutive outputs via float4
        float wx[4], wy[4], wxx[4], wyy[4], wxy[4];

        {
            const float4* p;
            float4 a, b, c4;
#define WIN5(SARR, WOUT)                                                     \
            p = reinterpret_cast<const float4*>(SARR + oc0);                 \
            a = p[0]; b = p[1]; c4 = p[2];                                   \
            WOUT[0] = a.x + a.y + a.z + a.w + b.x + b.y + b.z;               \
            WOUT[1] = WOUT[0] - a.x + b.w;                                   \
            WOUT[2] = WOUT[1] - a.y + c4.x;                                  \
            WOUT[3] = WOUT[2] - a.z + c4.y;

            WIN5(s_sx, wx)
            WIN5(s_sy, wy)
            WIN5(s_sxx, wxx)
            WIN5(s_syy, wyy)
            WIN5(s_sxy, wxy)
#undef WIN5
        }

        // SSIM per output; batch the 4 reciprocals into one MUFU.RCP
        float num[4], den[4];
#pragma unroll
        for (int i = 0; i < 4; i++) {
            const float ux = wx[i] * INV_NP;
            const float uy = wy[i] * INV_NP;
            const float uxx = wxx[i] * INV_NP;
            const float uyy = wyy[i] * INV_NP;
            const float uxy = wxy[i] * INV_NP;
            const float vx = COV_NORM * (uxx - ux * ux);
            const float vy = COV_NORM * (uyy - uy * uy);
            const float vxy = COV_NORM * (uxy - ux * uy);
            const float A = 2.0f * ux * uy + C1;
            const float B = 2.0f * vxy + C2;
            const float Cc = ux * ux + uy * uy + C1;
            const float D = vx + vy + C2;
            const bool valid = (oc0 + i) < OW;
            num[i] = valid ? A * B : 0.0f;
            den[i] = valid ? Cc * D : 1.0f;
        }
        const float p01 = den[0] * den[1];
        const float p012 = p01 * den[2];
        const float p0123 = p012 * den[3];
        const float rall = 1.0f / p0123;     // single reciprocal
        const float r3 = rall * p012;        // 1/den3
        const float r012 = rall * den[3];    // 1/(d0 d1 d2)
        const float r2 = r012 * p01;         // 1/den2
        const float r01 = r012 * den[2];     // 1/(d0 d1)
        const float r1 = r01 * den[0];       // 1/den1
        const float r0v = r01 * den[1];      // 1/den0

        acc += num[0] * r0v + num[1] * r1 + num[2] * r2 + num[3] * r3;
    }

    // block reduction -> double atomic accumulate
    red[t] = acc;
    __syncthreads();
#pragma unroll
    for (int s = THREADS / 2; s > 0; s >>= 1) {
        if (t < s) red[t] += red[t + s];
        __syncthreads();
    }
    if (t == 0) atomicAdd(&g_accum, (double)red[0]);
}

extern "C" void kernel_launch(void* const* d_in, const int* in_sizes, int n_in,
                              void* d_out, int out_size) {
    const float* x = (const float*)d_in[0];
    const float* y = (const float*)d_in[1];
    float* out = (float*)d_out;

    ssim_zero<<<1, 1>>>();
    dim3 grid(NBANDS, CH);
    ssim_main<<<grid, THREADS>>>(x, y);
    ssim_final<<<1, 1>>>(out);
}

// round 2
// speedup vs baseline: 1.1767x; 1.1767x over previous
#include <cuda_runtime.h>

namespace {
constexpr int W = 512, H = 512, OW = 506, OH = 506, CH = 96;
constexpr int BH = 64;
constexpr int NBANDS = (OH + BH - 1) / BH;   // 8
constexpr int THREADS = 128;
constexpr int NBLOCKS = NBANDS * CH;         // 768

constexpr float C1f = 0.01f * 0.01f;
constexpr float C2f = 0.03f * 0.03f;
constexpr float INV  = 1.0f / 49.0f;
constexpr float INV2 = INV * INV;
constexpr float COV  = 49.0f / 48.0f;
constexpr float kA  = 2.0f * INV2;           // A = kA*P + C1
constexpr float kC  = INV2;                  // C = kC*Q + C1
constexpr float kB1 = 2.0f * COV * INV;      // B = kB1*Sxy - kB2*P + C2
constexpr float kB2 = 2.0f * COV * INV2;
constexpr float kD1 = COV * INV;             // D = kD1*(Sxx+Syy) - kD2*Q + C2
constexpr float kD2 = COV * INV2;
}

__device__ double g_partials[NBLOCKS];
__device__ unsigned int g_count = 0;

__global__ __launch_bounds__(THREADS) void ssim_fused(const float* __restrict__ X,
                                                      const float* __restrict__ Y,
                                                      float* __restrict__ out) {
    const int ch = blockIdx.y, band = blockIdx.x;
    const int bid = ch * gridDim.x + band;
    const float* __restrict__ x = X + (size_t)ch * H * W;
    const float* __restrict__ y = Y + (size_t)ch * H * W;
    const int r0 = band * BH;
    const int rEnd = min(r0 + BH, OH);
    const int t = threadIdx.x;
    const int oc0 = 4 * t;

    __shared__ __align__(16) float sb[2][5][W + 8];  // ping-pong column-sum rows
    __shared__ double sred[THREADS];
    __shared__ bool isLast;

    // zero the 8-float pad of all 2x5 arrays (read by float4 windows of last threads)
    if (t < 16) {
        const int b = t & 1, pp = t >> 1;
#pragma unroll
        for (int q = 0; q < 5; q++) sb[b][q][W + pp] = 0.0f;
    }

    // vertical rolling column sums for 4 contiguous columns
    float sx[4], sy[4], sxx[4], syy[4], sxy[4];
#pragma unroll
    for (int j = 0; j < 4; j++) sx[j] = sy[j] = sxx[j] = syy[j] = sxy[j] = 0.0f;

#pragma unroll
    for (int rr = 0; rr < 7; rr++) {
        const float4 xv = *(const float4*)(x + (size_t)(r0 + rr) * W + oc0);
        const float4 yv = *(const float4*)(y + (size_t)(r0 + rr) * W + oc0);
        const float xa[4] = {xv.x, xv.y, xv.z, xv.w};
        const float ya[4] = {yv.x, yv.y, yv.z, yv.w};
#pragma unroll
        for (int j = 0; j < 4; j++) {
            sx[j] += xa[j];
            sy[j] += ya[j];
            sxx[j] = fmaf(xa[j], xa[j], sxx[j]);
            syy[j] = fmaf(ya[j], ya[j], syy[j]);
            sxy[j] = fmaf(xa[j], ya[j], sxy[j]);
        }
    }

    float acc = 0.0f;

    for (int r = r0; r < rEnd; r++) {
        const int buf = (r - r0) & 1;
        if (r > r0) {
            const float4 xn4 = *(const float4*)(x + (size_t)(r + 6) * W + oc0);
            const float4 yn4 = *(const float4*)(y + (size_t)(r + 6) * W + oc0);
            const float4 xo4 = *(const float4*)(x + (size_t)(r - 1) * W + oc0);
            const float4 yo4 = *(const float4*)(y + (size_t)(r - 1) * W + oc0);
            const float xn[4] = {xn4.x, xn4.y, xn4.z, xn4.w};
            const float yn[4] = {yn4.x, yn4.y, yn4.z, yn4.w};
            const float xo[4] = {xo4.x, xo4.y, xo4.z, xo4.w};
            const float yo[4] = {yo4.x, yo4.y, yo4.z, yo4.w};
#pragma unroll
            for (int j = 0; j < 4; j++) {
                sx[j] += xn[j] - xo[j];
                sy[j] += yn[j] - yo[j];
                sxx[j] = fmaf(xn[j], xn[j], sxx[j]);
                sxx[j] = fmaf(-xo[j], xo[j], sxx[j]);
                syy[j] = fmaf(yn[j], yn[j], syy[j]);
                syy[j] = fmaf(-yo[j], yo[j], syy[j]);
                sxy[j] = fmaf(xn[j], yn[j], sxy[j]);
                sxy[j] = fmaf(-xo[j], yo[j], sxy[j]);
            }
        }

        // vectorized column-sum publish
        *(float4*)&sb[buf][0][oc0] = make_float4(sx[0], sx[1], sx[2], sx[3]);
        *(float4*)&sb[buf][1][oc0] = make_float4(sy[0], sy[1], sy[2], sy[3]);
        *(float4*)&sb[buf][2][oc0] = make_float4(sxx[0], sxx[1], sxx[2], sxx[3]);
        *(float4*)&sb[buf][3][oc0] = make_float4(syy[0], syy[1], syy[2], syy[3]);
        *(float4*)&sb[buf][4][oc0] = make_float4(sxy[0], sxy[1], sxy[2], sxy[3]);
        __syncthreads();  // single barrier per row (ping-pong removes WAR sync)

        // horizontal 7-windows for 4 consecutive outputs (3 LDS.128 per quantity)
        float wv[5][4];
#pragma unroll
        for (int q = 0; q < 5; q++) {
            const float4* p = (const float4*)(&sb[buf][q][oc0]);
            const float4 a = p[0], b = p[1], c4 = p[2];
            wv[q][0] = a.x + a.y + a.z + a.w + b.x + b.y + b.z;
            wv[q][1] = wv[q][0] - a.x + b.w;
            wv[q][2] = wv[q][1] - a.y + c4.x;
            wv[q][3] = wv[q][2] - a.z + c4.y;
        }

        float num[4], den[4];
#pragma unroll
        for (int i = 0; i < 4; i++) {
            const float Sx = wv[0][i], Sy = wv[1][i];
            const float Sxx = wv[2][i], Syy = wv[3][i], Sxy = wv[4][i];
            const float P = Sx * Sy;
            const float Q = fmaf(Sx, Sx, Sy * Sy);
            const float A = fmaf(kA, P, C1f);
            const float Cc = fmaf(kC, Q, C1f);
            const float B = fmaf(kB1, Sxy, fmaf(-kB2, P, C2f));
            const float D = fmaf(kD1, Sxx + Syy, fmaf(-kD2, Q, C2f));
            const bool valid = (oc0 + i) < OW;
            num[i] = valid ? A * B : 0.0f;
            den[i] = valid ? Cc * D : 1.0f;
        }
        // one MUFU.RCP for 4 pixels
        const float p01 = den[0] * den[1];
        const float p012 = p01 * den[2];
        const float rall = 1.0f / (p012 * den[3]);
        const float r3 = rall * p012;
        const float r012 = rall * den[3];
        const float r2 = r012 * p01;
        const float r01 = r012 * den[2];
        acc += num[0] * (r01 * den[1]) + num[1] * (r01 * den[0]) + num[2] * r2 + num[3] * r3;
    }

    // block tree-reduce in double
    sred[t] = (double)acc;
    __syncthreads();
#pragma unroll
    for (int s = THREADS / 2; s > 0; s >>= 1) {
        if (t < s) sred[t] += sred[t + s];
        __syncthreads();
    }
    if (t == 0) {
        g_partials[bid] = sred[0];
        __threadfence();
        const unsigned int c = atomicInc(&g_count, NBLOCKS - 1);  // wraps back to 0
        isLast = (c == NBLOCKS - 1);
    }
    __syncthreads();

    if (isLast) {
        // last block: reduce all partials, write output (deterministic order)
        const volatile double* vp = g_partials;
        double s = 0.0;
        for (int i = t; i < NBLOCKS; i += THREADS) s += vp[i];
        sred[t] = s;
        __syncthreads();
#pragma unroll
        for (int sdim = THREADS / 2; sdim > 0; sdim >>= 1) {
            if (t < sdim) sred[t] += sred[t + sdim];
            __syncthreads();
        }
        if (t == 0)
            out[0] = (float)(sred[0] / ((double)CH * (double)OH * (double)OW));
    }
}

extern "C" void kernel_launch(void* const* d_in, const int* in_sizes, int n_in,
                              void* d_out, int out_size) {
    const float* x = (const float*)d_in[0];
    const float* y = (const float*)d_in[1];
    float* out = (float*)d_out;
    dim3 grid(NBANDS, CH);
    ssim_fused<<<grid, THREADS>>>(x, y, out);
}

// round 3
// speedup vs baseline: 1.6515x; 1.4035x over previous
#include <cuda_runtime.h>

namespace {
constexpr int W = 512, H = 512, OW = 506, OH = 506, CH = 96;
constexpr int NB = 16;                 // bands per channel
constexpr int BH = 32;                 // rows per band (last band: 26)
constexpr int NWARPS = CH * NB;        // 1536 independent warps

constexpr float C1f = 0.01f * 0.01f;
constexpr float C2f = 0.03f * 0.03f;
constexpr float INV  = 1.0f / 49.0f;
constexpr float INV2 = INV * INV;
constexpr float COV  = 49.0f / 48.0f;
constexpr float kA  = 2.0f * INV2;
constexpr float kC  = INV2;
constexpr float kB1 = 2.0f * COV * INV;
constexpr float kB2 = 2.0f * COV * INV2;
constexpr float kD1 = COV * INV;
constexpr float kD2 = COV * INV2;
}

__device__ double g_partials[NWARPS];
__device__ unsigned int g_count = 0;

__global__ __launch_bounds__(32, 10) void ssim_warp(const float* __restrict__ X,
                                                    const float* __restrict__ Y,
                                                    float* __restrict__ out) {
    const int wid = blockIdx.x;
    const int ch = wid >> 4;           // / NB
    const int band = wid & (NB - 1);
    const int lane = threadIdx.x;
    const float* __restrict__ x = X + (size_t)ch * H * W;
    const float* __restrict__ y = Y + (size_t)ch * H * W;
    const int r0 = band * BH;
    const int rEnd = min(r0 + BH, OH);
    const int c0 = lane << 4;          // 16 contiguous columns per lane

    // register-resident vertical column sums: Sx, Sy, Sxx, Syy, Sxy x 16 cols
    float s[5][16];
#pragma unroll
    for (int q = 0; q < 5; q++)
#pragma unroll
        for (int i = 0; i < 16; i++) s[q][i] = 0.0f;

    // prologue: accumulate 7 input rows
#pragma unroll
    for (int rr = 0; rr < 7; rr++) {
        const float4* xr = (const float4*)(x + (size_t)(r0 + rr) * W + c0);
        const float4* yr = (const float4*)(y + (size_t)(r0 + rr) * W + c0);
#pragma unroll
        for (int v = 0; v < 4; v++) {
            const float4 xv = xr[v], yv = yr[v];
            const float xa[4] = {xv.x, xv.y, xv.z, xv.w};
            const float ya[4] = {yv.x, yv.y, yv.z, yv.w};
#pragma unroll
            for (int j = 0; j < 4; j++) {
                const int i = v * 4 + j;
                s[0][i] += xa[j];
                s[1][i] += ya[j];
                s[2][i] = fmaf(xa[j], xa[j], s[2][i]);
                s[3][i] = fmaf(ya[j], ya[j], s[3][i]);
                s[4][i] = fmaf(xa[j], ya[j], s[4][i]);
            }
        }
    }

    float acc = 0.0f;

    for (int r = r0; r < rEnd; r++) {
        if (r > r0) {
            // roll vertical sums: + row(r+6), - row(r-1)
            const float4* xn = (const float4*)(x + (size_t)(r + 6) * W + c0);
            const float4* yn = (const float4*)(y + (size_t)(r + 6) * W + c0);
            const float4* xo = (const float4*)(x + (size_t)(r - 1) * W + c0);
            const float4* yo = (const float4*)(y + (size_t)(r - 1) * W + c0);
#pragma unroll
            for (int v = 0; v < 4; v++) {
                const float4 a = xn[v], b = yn[v], c = xo[v], d = yo[v];
                const float na[4] = {a.x, a.y, a.z, a.w};
                const float nb[4] = {b.x, b.y, b.z, b.w};
                const float oa[4] = {c.x, c.y, c.z, c.w};
                const float ob[4] = {d.x, d.y, d.z, d.w};
#pragma unroll
                for (int j = 0; j < 4; j++) {
                    const int i = v * 4 + j;
                    s[0][i] += na[j] - oa[j];
                    s[1][i] += nb[j] - ob[j];
                    s[2][i] = fmaf(na[j], na[j], s[2][i]);
                    s[2][i] = fmaf(-oa[j], oa[j], s[2][i]);
                    s[3][i] = fmaf(nb[j], nb[j], s[3][i]);
                    s[3][i] = fmaf(-ob[j], ob[j], s[3][i]);
                    s[4][i] = fmaf(na[j], nb[j], s[4][i]);
                    s[4][i] = fmaf(-oa[j], ob[j], s[4][i]);
                }
            }
        }

        // sliding horizontal 7-windows; remote cols (16..21) via shfl from lane+1
        float wq[5];
#pragma unroll
        for (int q = 0; q < 5; q++)
            wq[q] = s[q][0] + s[q][1] + s[q][2] + s[q][3] + s[q][4] + s[q][5] + s[q][6];

#pragma unroll
        for (int half = 0; half < 2; half++) {
            float num[8], den[8];
#pragma unroll
            for (int k = 0; k < 8; k++) {
                const int i = half * 8 + k;
                if (i > 0) {
#pragma unroll
                    for (int q = 0; q < 5; q++) {
                        float add;
                        if (i + 6 < 16) {
                            add = s[q][i + 6];
                        } else {
                            // warp-uniform shuffle; lane31's garbage only feeds masked outputs
                            add = __shfl_down_sync(0xffffffffu, s[q][i - 10], 1);
                        }
                        wq[q] += add - s[q][i - 1];
                    }
                }
                const float Sx = wq[0], Sy = wq[1];
                const float Sxx = wq[2], Syy = wq[3], Sxy = wq[4];
                const float P = Sx * Sy;
                const float Q = fmaf(Sx, Sx, Sy * Sy);
                const float A = fmaf(kA, P, C1f);
                const float Cc = fmaf(kC, Q, C1f);
                const float B = fmaf(kB1, Sxy, fmaf(-kB2, P, C2f));
                const float D = fmaf(kD1, Sxx + Syy, fmaf(-kD2, Q, C2f));
                const bool valid = (c0 + i) < OW;
                num[k] = valid ? A * B : 0.0f;
                den[k] = valid ? Cc * D : 1.0f;
            }
            // one MUFU.RCP for 8 pixels: prefix/suffix product trick
            float pre[8];
            pre[0] = 1.0f;
#pragma unroll
            for (int k = 1; k < 8; k++) pre[k] = pre[k - 1] * den[k - 1];
            const float rall = 1.0f / (pre[7] * den[7]);
            float suf = 1.0f;
            float partial = 0.0f;
#pragma unroll
            for (int k = 7; k >= 0; k--) {
                partial = fmaf(num[k], pre[k] * suf, partial);
                suf *= den[k];
            }
            acc = fmaf(partial, rall, acc);
        }
    }

    // warp tree-reduce (fixed order -> deterministic)
#pragma unroll
    for (int off = 16; off > 0; off >>= 1)
        acc += __shfl_down_sync(0xffffffffu, acc, off);

    int last = 0;
    if (lane == 0) {
        g_partials[wid] = (double)acc;
        __threadfence();
        const unsigned int c = atomicInc(&g_count, NWARPS - 1);  // wraps to 0
        last = (c == NWARPS - 1) ? 1 : 0;
    }
    last = __shfl_sync(0xffffffffu, last, 0);

    if (last) {
        // last warp reduces all partials in a fixed order -> deterministic
        const volatile double* vp = g_partials;
        double sd = 0.0;
        for (int i = lane; i < NWARPS; i += 32) sd += vp[i];
#pragma unroll
        for (int off = 16; off > 0; off >>= 1)
            sd += __shfl_down_sync(0xffffffffu, sd, off);
        if (lane == 0)
            out[0] = (float)(sd / ((double)CH * (double)OH * (double)OW));
    }
}

extern "C" void kernel_launch(void* const* d_in, const int* in_sizes, int n_in,
                              void* d_out, int out_size) {
    const float* x = (const float*)d_in[0];
    const float* y = (const float*)d_in[1];
    float* out = (float*)d_out;
    ssim_warp<<<NWARPS, 32>>>(x, y, out);
}